// round 2
// baseline (speedup 1.0000x reference)
#include <cuda_runtime.h>
#include <math.h>

#define S_LEN 2048
#define HID   4096
#define NH    32
#define NKV   8
#define HDIM  128
#define WINDOW 1024

// Scratch (allocation-free rule: __device__ globals)
__device__ float g_Q[S_LEN * HID];          // 32 MB
__device__ float g_K[S_LEN * NKV * HDIM];   // 8 MB
__device__ float g_V[S_LEN * NKV * HDIM];   // 8 MB
__device__ float g_att[S_LEN * HID];        // 32 MB

// ---------------------------------------------------------------------------
// C[M][N] = A[M][K] * B[N][K]^T      (A row-major MxK, B row-major NxK)
// 128x128 tile, BK=16, 256 threads, 8x8 register micro-tile.
// ---------------------------------------------------------------------------
#define BM 128
#define BN 128
#define BK 16

__global__ void __launch_bounds__(256, 2)
sgemm_nt(const float* __restrict__ A, const float* __restrict__ B,
         float* __restrict__ C, int M, int N, int K)
{
    __shared__ float As[BK][BM];
    __shared__ float Bs[BK][BN];

    const int tid = threadIdx.x;
    const int m0 = blockIdx.y * BM;
    const int n0 = blockIdx.x * BN;
    const int tx = tid & 15;       // 0..15 -> n
    const int ty = tid >> 4;       // 0..15 -> m

    const int lr = tid >> 2;           // 0..63 row within tile (two passes)
    const int lc = (tid & 3) * 4;      // k offset (float4)

    float acc[8][8];
    #pragma unroll
    for (int i = 0; i < 8; ++i)
        #pragma unroll
        for (int j = 0; j < 8; ++j) acc[i][j] = 0.f;

    for (int k0 = 0; k0 < K; k0 += BK) {
        #pragma unroll
        for (int p = 0; p < BM / 64; ++p) {
            float4 v = *(const float4*)&A[(size_t)(m0 + lr + p * 64) * K + k0 + lc];
            As[lc + 0][lr + p * 64] = v.x;
            As[lc + 1][lr + p * 64] = v.y;
            As[lc + 2][lr + p * 64] = v.z;
            As[lc + 3][lr + p * 64] = v.w;
        }
        #pragma unroll
        for (int p = 0; p < BN / 64; ++p) {
            float4 v = *(const float4*)&B[(size_t)(n0 + lr + p * 64) * K + k0 + lc];
            Bs[lc + 0][lr + p * 64] = v.x;
            Bs[lc + 1][lr + p * 64] = v.y;
            Bs[lc + 2][lr + p * 64] = v.z;
            Bs[lc + 3][lr + p * 64] = v.w;
        }
        __syncthreads();

        #pragma unroll
        for (int k = 0; k < BK; ++k) {
            float a[8], b[8];
            *(float4*)&a[0] = *(const float4*)&As[k][ty * 8];
            *(float4*)&a[4] = *(const float4*)&As[k][ty * 8 + 4];
            *(float4*)&b[0] = *(const float4*)&Bs[k][tx * 8];
            *(float4*)&b[4] = *(const float4*)&Bs[k][tx * 8 + 4];
            #pragma unroll
            for (int i = 0; i < 8; ++i)
                #pragma unroll
                for (int j = 0; j < 8; ++j)
                    acc[i][j] += a[i] * b[j];
        }
        __syncthreads();
    }

    #pragma unroll
    for (int i = 0; i < 8; ++i) {
        float* crow = &C[(size_t)(m0 + ty * 8 + i) * N + n0 + tx * 8];
        float4 v0 = make_float4(acc[i][0], acc[i][1], acc[i][2], acc[i][3]);
        float4 v1 = make_float4(acc[i][4], acc[i][5], acc[i][6], acc[i][7]);
        *(float4*)&crow[0] = v0;
        *(float4*)&crow[4] = v1;
    }
}

// ---------------------------------------------------------------------------
// RoPE in place on X[token][h*128 + d], pair (d, d+64), d<64.
// ---------------------------------------------------------------------------
__global__ void rope_kernel(float* __restrict__ X, const int* __restrict__ pos_ids,
                            int nheads)
{
    int idx = blockIdx.x * blockDim.x + threadIdx.x;
    int total = S_LEN * nheads * 64;
    if (idx >= total) return;
    int d = idx % 64;
    int h = (idx / 64) % nheads;
    int t = idx / (64 * nheads);

    // inv_freq = 10000^(-d/64) = exp(-d * ln(10000)/64)
    float invf = expf(-(float)d * 0.14391156831212787f);
    float ang = (float)pos_ids[t] * invf;
    float s, c;
    sincosf(ang, &s, &c);

    float* base = X + (size_t)t * nheads * HDIM + h * HDIM;
    float x0 = base[d];
    float x1 = base[d + 64];
    base[d]      = x0 * c - x1 * s;
    base[d + 64] = x1 * c + x0 * s;
}

// ---------------------------------------------------------------------------
// Flash attention, fp32. Block = (head, 64-row q tile), 256 threads.
// Qs/Ks stored d-major [128][64]; Vs row-major [64][128]; Ss [64][64].
// ---------------------------------------------------------------------------
__global__ void __launch_bounds__(256)
attn_kernel(const float* __restrict__ Q, const float* __restrict__ K,
            const float* __restrict__ V, float* __restrict__ O)
{
    extern __shared__ float sm[];
    float* Qs   = sm;                 // [128][64]
    float* Ks   = Qs + 128 * 64;      // [128][64]
    float* Vs   = Ks + 128 * 64;      // [64][128]
    float* Ss   = Vs + 64 * 128;      // [64][64]
    float* mrow = Ss + 64 * 64;       // [64]
    float* lrow = mrow + 64;          // [64]
    float* arow = lrow + 64;          // [64]

    const int qt  = blockIdx.x;
    const int h   = blockIdx.y;
    const int m0  = qt * 64;
    const int kvh = h >> 2;           // GROUPS = 4
    const int tid = threadIdx.x;
    const int tx  = tid & 15;
    const int ty  = tid >> 4;
    const float scale = 0.08838834764831845f;  // 1/sqrt(128)

    // Load + scale Q tile (d-major into smem)
    #pragma unroll
    for (int t = 0; t < 8; ++t) {
        int linear = tid + t * 256;       // 2048 float4 units
        int r  = linear >> 5;
        int d4 = (linear & 31) * 4;
        float4 v = *(const float4*)&Q[(size_t)(m0 + r) * HID + h * HDIM + d4];
        Qs[(d4 + 0) * 64 + r] = v.x * scale;
        Qs[(d4 + 1) * 64 + r] = v.y * scale;
        Qs[(d4 + 2) * 64 + r] = v.z * scale;
        Qs[(d4 + 3) * 64 + r] = v.w * scale;
    }
    if (tid < 64) { mrow[tid] = -INFINITY; lrow[tid] = 0.f; }

    float acc[4][8];
    #pragma unroll
    for (int i = 0; i < 4; ++i)
        #pragma unroll
        for (int j = 0; j < 8; ++j) acc[i][j] = 0.f;

    const int j0 = (qt >= 16) ? qt - 16 : 0;
    for (int j = j0; j <= qt; ++j) {
        __syncthreads();   // protect Ks/Vs/Ss from previous iteration consumers

        // Load K (d-major) and V (row-major) tiles
        #pragma unroll
        for (int t = 0; t < 8; ++t) {
            int linear = tid + t * 256;
            int r  = linear >> 5;
            int d4 = (linear & 31) * 4;
            size_t goff = (size_t)(j * 64 + r) * (NKV * HDIM) + kvh * HDIM + d4;
            float4 kv = *(const float4*)&K[goff];
            Ks[(d4 + 0) * 64 + r] = kv.x;
            Ks[(d4 + 1) * 64 + r] = kv.y;
            Ks[(d4 + 2) * 64 + r] = kv.z;
            Ks[(d4 + 3) * 64 + r] = kv.w;
            *(float4*)&Vs[r * 128 + d4] = *(const float4*)&V[goff];
        }
        __syncthreads();

        // S = (Q*scale) K^T, 4x4 per thread
        float s[4][4];
        #pragma unroll
        for (int i = 0; i < 4; ++i)
            #pragma unroll
            for (int jj = 0; jj < 4; ++jj) s[i][jj] = 0.f;

        for (int k = 0; k < 128; ++k) {
            float a[4], b[4];
            *(float4*)a = *(const float4*)&Qs[k * 64 + ty * 4];
            *(float4*)b = *(const float4*)&Ks[k * 64 + tx * 4];
            #pragma unroll
            for (int i = 0; i < 4; ++i)
                #pragma unroll
                for (int jj = 0; jj < 4; ++jj)
                    s[i][jj] += a[i] * b[jj];
        }

        // Mask (causal + sliding window) and spill to smem
        #pragma unroll
        for (int i = 0; i < 4; ++i) {
            int qi = m0 + ty * 4 + i;
            #pragma unroll
            for (int jj = 0; jj < 4; ++jj) {
                int c = j * 64 + tx * 4 + jj;
                bool vis = (c <= qi) && (qi - c < WINDOW);
                Ss[(ty * 4 + i) * 64 + tx * 4 + jj] = vis ? s[i][jj] : -INFINITY;
            }
        }
        __syncthreads();

        // Online softmax update: 4 threads per row
        {
            int r  = tid >> 2;
            int q4 = tid & 3;
            float vals[16];
            float tmax = -INFINITY;
            #pragma unroll
            for (int cidx = 0; cidx < 16; ++cidx) {
                vals[cidx] = Ss[r * 64 + q4 * 16 + cidx];
                tmax = fmaxf(tmax, vals[cidx]);
            }
            tmax = fmaxf(tmax, __shfl_xor_sync(0xffffffffu, tmax, 1));
            tmax = fmaxf(tmax, __shfl_xor_sync(0xffffffffu, tmax, 2));

            float mold = mrow[r];
            float mnew = fmaxf(mold, tmax);
            float alpha;
            float lsum = 0.f;
            if (mnew == -INFINITY) {
                // whole row masked so far (window boundary tile): contribute nothing
                alpha = 1.f;
                #pragma unroll
                for (int cidx = 0; cidx < 16; ++cidx)
                    Ss[r * 64 + q4 * 16 + cidx] = 0.f;
            } else {
                alpha = __expf(mold - mnew);   // expf(-inf)=0, safe
                #pragma unroll
                for (int cidx = 0; cidx < 16; ++cidx) {
                    float p = __expf(vals[cidx] - mnew);  // -inf -> 0
                    Ss[r * 64 + q4 * 16 + cidx] = p;
                    lsum += p;
                }
            }
            lsum += __shfl_xor_sync(0xffffffffu, lsum, 1);
            lsum += __shfl_xor_sync(0xffffffffu, lsum, 2);
            if (q4 == 0) {
                mrow[r] = mnew;
                lrow[r] = lrow[r] * alpha + lsum;
                arow[r] = alpha;
            }
        }
        __syncthreads();

        // O = O*alpha + P @ V     (rows ty*4.., dims tx*8..)
        #pragma unroll
        for (int i = 0; i < 4; ++i) {
            float al = arow[ty * 4 + i];
            #pragma unroll
            for (int jj = 0; jj < 8; ++jj) acc[i][jj] *= al;
        }
        for (int c = 0; c < 64; ++c) {
            float p[4], v[8];
            #pragma unroll
            for (int i = 0; i < 4; ++i) p[i] = Ss[(ty * 4 + i) * 64 + c];
            *(float4*)&v[0] = *(const float4*)&Vs[c * 128 + tx * 8];
            *(float4*)&v[4] = *(const float4*)&Vs[c * 128 + tx * 8 + 4];
            #pragma unroll
            for (int i = 0; i < 4; ++i)
                #pragma unroll
                for (int jj = 0; jj < 8; ++jj)
                    acc[i][jj] += p[i] * v[jj];
        }
    }

    // Normalize and store: O[token][h*128 + d]
    #pragma unroll
    for (int i = 0; i < 4; ++i) {
        int r = ty * 4 + i;
        float inv = 1.f / lrow[r];
        float4 o0 = make_float4(acc[i][0] * inv, acc[i][1] * inv,
                                acc[i][2] * inv, acc[i][3] * inv);
        float4 o1 = make_float4(acc[i][4] * inv, acc[i][5] * inv,
                                acc[i][6] * inv, acc[i][7] * inv);
        float* op = &O[(size_t)(m0 + r) * HID + h * HDIM + tx * 8];
        *(float4*)&op[0] = o0;
        *(float4*)&op[4] = o1;
    }
}

// ---------------------------------------------------------------------------
extern "C" void kernel_launch(void* const* d_in, const int* in_sizes, int n_in,
                              void* d_out, int out_size)
{
    const float* hs  = (const float*)d_in[0];
    // d_in[1] = attention_mask (sliding-window causal, reproduced analytically)
    const int*   pos = (const int*)d_in[2];
    const float* Wq  = (const float*)d_in[3];
    const float* Wk  = (const float*)d_in[4];
    const float* Wv  = (const float*)d_in[5];
    const float* Wo  = (const float*)d_in[6];
    float* out = (float*)d_out;

    float *qb, *kb, *vb, *ab;
    cudaGetSymbolAddress((void**)&qb, g_Q);
    cudaGetSymbolAddress((void**)&kb, g_K);
    cudaGetSymbolAddress((void**)&vb, g_V);
    cudaGetSymbolAddress((void**)&ab, g_att);

    const int attn_smem = (128 * 64 * 2 + 64 * 128 + 64 * 64 + 3 * 64) * (int)sizeof(float);
    cudaFuncSetAttribute(attn_kernel, cudaFuncAttributeMaxDynamicSharedMemorySize, attn_smem);

    // Projections
    sgemm_nt<<<dim3(HID / BN, S_LEN / BM), 256>>>(hs, Wq, qb, S_LEN, HID, HID);
    sgemm_nt<<<dim3((NKV * HDIM) / BN, S_LEN / BM), 256>>>(hs, Wk, kb, S_LEN, NKV * HDIM, HID);
    sgemm_nt<<<dim3((NKV * HDIM) / BN, S_LEN / BM), 256>>>(hs, Wv, vb, S_LEN, NKV * HDIM, HID);

    // RoPE
    {
        int totq = S_LEN * NH * 64;
        rope_kernel<<<(totq + 255) / 256, 256>>>(qb, pos, NH);
        int totk = S_LEN * NKV * 64;
        rope_kernel<<<(totk + 255) / 256, 256>>>(kb, pos, NKV);
    }

    // Attention
    attn_kernel<<<dim3(S_LEN / 64, NH), 256, attn_smem>>>(qb, kb, vb, ab);

    // Output projection
    sgemm_nt<<<dim3(HID / BN, S_LEN / BM), 256>>>(ab, Wo, out, S_LEN, HID, HID);
}

// round 6
// speedup vs baseline: 1.9614x; 1.9614x over previous
#include <cuda_runtime.h>
#include <cuda_bf16.h>
#include <math.h>
#include <stdint.h>

#define S_LEN 2048
#define HID   4096
#define NH    32
#define NKV   8
#define HDIM  128
#define WINDOW 1024
#define KDIM  4096

// ---------------- scratch (__device__ globals; no allocation) ----------------
__device__ float g_Q[S_LEN * HID];
__device__ float g_K[S_LEN * NKV * HDIM];
__device__ float g_V[S_LEN * NKV * HDIM];
__device__ float g_att[S_LEN * HID];

__device__ __align__(256) __nv_bfloat16 g_hs_hi[S_LEN * HID];
__device__ __align__(256) __nv_bfloat16 g_hs_lo[S_LEN * HID];
__device__ __align__(256) __nv_bfloat16 g_att_hi[S_LEN * HID];
__device__ __align__(256) __nv_bfloat16 g_att_lo[S_LEN * HID];
__device__ __align__(256) __nv_bfloat16 g_Wq_hi[HID * HID];
__device__ __align__(256) __nv_bfloat16 g_Wq_lo[HID * HID];
__device__ __align__(256) __nv_bfloat16 g_Wk_hi[NKV * HDIM * HID];
__device__ __align__(256) __nv_bfloat16 g_Wk_lo[NKV * HDIM * HID];
__device__ __align__(256) __nv_bfloat16 g_Wv_hi[NKV * HDIM * HID];
__device__ __align__(256) __nv_bfloat16 g_Wv_lo[NKV * HDIM * HID];
__device__ __align__(256) __nv_bfloat16 g_Wo_hi[HID * HID];
__device__ __align__(256) __nv_bfloat16 g_Wo_lo[HID * HID];

// ---------------- helpers (baseline PTX only: sm_80-class features) ----------
__device__ __forceinline__ uint32_t smem_u32(const void* p) {
    uint32_t a;
    asm("{ .reg .u64 t; cvta.to.shared.u64 t, %1; cvt.u32.u64 %0, t; }" : "=r"(a) : "l"(p));
    return a;
}
__device__ __forceinline__ void cp16(uint32_t dst, const void* src) {
    asm volatile("cp.async.cg.shared.global [%0], [%1], 16;" :: "r"(dst), "l"(src));
}
__device__ __forceinline__ void cp_commit() {
    asm volatile("cp.async.commit_group;" ::: "memory");
}
template <int N>
__device__ __forceinline__ void cp_wait() {
    asm volatile("cp.async.wait_group %0;" :: "n"(N) : "memory");
}
__device__ __forceinline__ void ldsm_x4(uint32_t* r, uint32_t addr) {
    asm volatile("ldmatrix.sync.aligned.m8n8.x4.shared.b16 {%0,%1,%2,%3}, [%4];"
                 : "=r"(r[0]), "=r"(r[1]), "=r"(r[2]), "=r"(r[3]) : "r"(addr));
}
__device__ __forceinline__ void mma16816(float* c, const uint32_t* a,
                                         uint32_t b0, uint32_t b1) {
    asm volatile(
        "mma.sync.aligned.m16n8k16.row.col.f32.bf16.bf16.f32 "
        "{%0,%1,%2,%3}, {%4,%5,%6,%7}, {%8,%9}, {%0,%1,%2,%3};"
        : "+f"(c[0]), "+f"(c[1]), "+f"(c[2]), "+f"(c[3])
        : "r"(a[0]), "r"(a[1]), "r"(a[2]), "r"(a[3]), "r"(b0), "r"(b1));
}

#define SWZ(off) ((off) ^ (((off) >> 3) & 0x70))

// ---------------------------------------------------------------------------
// split fp32 -> bf16 hi + bf16 lo (residual)
// ---------------------------------------------------------------------------
__global__ void split_kernel(const float* __restrict__ in,
                             __nv_bfloat16* __restrict__ hi,
                             __nv_bfloat16* __restrict__ lo, int n4)
{
    int i = blockIdx.x * blockDim.x + threadIdx.x;
    if (i >= n4) return;
    float4 v = ((const float4*)in)[i];
    float x[4] = {v.x, v.y, v.z, v.w};
    unsigned short h[4], l[4];
    #pragma unroll
    for (int j = 0; j < 4; ++j) {
        __nv_bfloat16 hb = __float2bfloat16(x[j]);
        __nv_bfloat16 lb = __float2bfloat16(x[j] - __bfloat162float(hb));
        h[j] = __bfloat16_as_ushort(hb);
        l[j] = __bfloat16_as_ushort(lb);
    }
    ((ushort4*)hi)[i] = make_ushort4(h[0], h[1], h[2], h[3]);
    ((ushort4*)lo)[i] = make_ushort4(l[0], l[1], l[2], l[3]);
}

// ---------------------------------------------------------------------------
// C[M][N] = (Ahi+Alo)[M][K] * (Bhi+Blo)[N][K]^T  via mma.sync bf16 (3 products)
// CTA 128x128, K-chunk 64, 8 warps (warp tile 64x32), cp.async double buffer.
// ---------------------------------------------------------------------------
#define GK 64
#define TILEB 16384                 // 128 rows x 128 bytes
#define BUFB (4 * TILEB)            // Ahi, Alo, Bhi, Blo

__global__ void __launch_bounds__(256, 1)
gemm_bf16x3(const __nv_bfloat16* __restrict__ Ahi, const __nv_bfloat16* __restrict__ Alo,
            const __nv_bfloat16* __restrict__ Bhi, const __nv_bfloat16* __restrict__ Blo,
            float* __restrict__ C, int M, int N, int K)
{
    extern __shared__ char smraw[];
    char* smc = (char*)(((uintptr_t)smraw + 1023) & ~(uintptr_t)1023);
    const uint32_t sbase = smem_u32(smc);

    const int tid = threadIdx.x;
    const int lane = tid & 31;
    const int wid = tid >> 5;
    const int wr = wid >> 2;            // 0..1 -> 64 rows each
    const int wc = wid & 3;             // 0..3 -> 32 cols each
    const int m0 = blockIdx.y * 128;
    const int n0 = blockIdx.x * 128;

    float acc[4][4][4];
    #pragma unroll
    for (int a = 0; a < 4; ++a)
        #pragma unroll
        for (int b = 0; b < 4; ++b)
            #pragma unroll
            for (int c = 0; c < 4; ++c) acc[a][b][c] = 0.f;

    const int NCHUNK = K / GK;

    // --- loader: 4 tiles x 1024 float4, swizzled cp.async ---
    auto load_chunk = [&](int it) {
        const uint32_t bufb = sbase + (it & 1) * BUFB;
        const int k0 = it * GK;
        #pragma unroll
        for (int p = 0; p < 4; ++p) {
            int linear = tid + p * 256;
            int r = linear >> 3;
            int cb = (linear & 7) * 16;          // byte col within 128B row
            uint32_t sw = SWZ((uint32_t)(r * 128 + cb));
            size_t ga = (size_t)(m0 + r) * K + k0 + (cb >> 1);
            size_t gb = (size_t)(n0 + r) * K + k0 + (cb >> 1);
            cp16(bufb + sw,              &Ahi[ga]);
            cp16(bufb + TILEB + sw,      &Alo[ga]);
            cp16(bufb + 2 * TILEB + sw,  &Bhi[gb]);
            cp16(bufb + 3 * TILEB + sw,  &Blo[gb]);
        }
    };

    load_chunk(0);
    cp_commit();

    const int lrow = lane & 15;            // row within 16-row ldmatrix footprint
    const int lkb  = (lane >> 4) * 16;     // k-half byte offset

    for (int it = 0; it < NCHUNK; ++it) {
        if (it + 1 < NCHUNK) {
            load_chunk(it + 1);
            cp_commit();
            cp_wait<1>();
        } else {
            cp_wait<0>();
        }
        __syncthreads();

        const uint32_t bufb = sbase + (it & 1) * BUFB;

        #pragma unroll
        for (int ks = 0; ks < 4; ++ks) {
            uint32_t ah[4][4], al[4][4], bh[2][4], bl[2][4];
            #pragma unroll
            for (int mi = 0; mi < 4; ++mi) {
                uint32_t off = (uint32_t)((wr * 64 + mi * 16 + lrow) * 128 + ks * 32 + lkb);
                uint32_t sw = SWZ(off);
                ldsm_x4(ah[mi], bufb + sw);
                ldsm_x4(al[mi], bufb + TILEB + sw);
            }
            #pragma unroll
            for (int np = 0; np < 2; ++np) {
                uint32_t off = (uint32_t)((wc * 32 + np * 16 + lrow) * 128 + ks * 32 + lkb);
                uint32_t sw = SWZ(off);
                ldsm_x4(bh[np], bufb + 2 * TILEB + sw);
                ldsm_x4(bl[np], bufb + 3 * TILEB + sw);
            }
            #pragma unroll
            for (int mi = 0; mi < 4; ++mi)
                #pragma unroll
                for (int ni = 0; ni < 4; ++ni) {
                    uint32_t b0h = bh[ni >> 1][ni & 1], b1h = bh[ni >> 1][2 + (ni & 1)];
                    uint32_t b0l = bl[ni >> 1][ni & 1], b1l = bl[ni >> 1][2 + (ni & 1)];
                    mma16816(acc[mi][ni], ah[mi], b0h, b1h);   // hi*hi
                    mma16816(acc[mi][ni], ah[mi], b0l, b1l);   // hi*lo
                    mma16816(acc[mi][ni], al[mi], b0h, b1h);   // lo*hi
                }
        }
        __syncthreads();
    }

    // epilogue
    const int row_base = m0 + wr * 64 + (lane >> 2);
    const int col_base = n0 + wc * 32 + (lane & 3) * 2;
    #pragma unroll
    for (int mi = 0; mi < 4; ++mi)
        #pragma unroll
        for (int ni = 0; ni < 4; ++ni) {
            int r = row_base + mi * 16;
            int cc = col_base + ni * 8;
            float2 v0 = make_float2(acc[mi][ni][0], acc[mi][ni][1]);
            float2 v1 = make_float2(acc[mi][ni][2], acc[mi][ni][3]);
            *(float2*)&C[(size_t)r * N + cc]       = v0;
            *(float2*)&C[(size_t)(r + 8) * N + cc] = v1;
        }
}

// ---------------------------------------------------------------------------
// RoPE in place on X[token][h*128 + d], pair (d, d+64), d<64.
// ---------------------------------------------------------------------------
__global__ void rope_kernel(float* __restrict__ X, const int* __restrict__ pos_ids,
                            int nheads)
{
    int idx = blockIdx.x * blockDim.x + threadIdx.x;
    int total = S_LEN * nheads * 64;
    if (idx >= total) return;
    int d = idx % 64;
    int h = (idx / 64) % nheads;
    int t = idx / (64 * nheads);

    float invf = expf(-(float)d * 0.14391156831212787f);
    float ang = (float)pos_ids[t] * invf;
    float s, c;
    sincosf(ang, &s, &c);

    float* base = X + (size_t)t * nheads * HDIM + h * HDIM;
    float x0 = base[d];
    float x1 = base[d + 64];
    base[d]      = x0 * c - x1 * s;
    base[d + 64] = x1 * c + x0 * s;
}

// ---------------------------------------------------------------------------
// Flash attention, fp32 (unchanged).
// ---------------------------------------------------------------------------
__global__ void __launch_bounds__(256)
attn_kernel(const float* __restrict__ Q, const float* __restrict__ K,
            const float* __restrict__ V, float* __restrict__ O)
{
    extern __shared__ float sm[];
    float* Qs   = sm;
    float* Ks   = Qs + 128 * 64;
    float* Vs   = Ks + 128 * 64;
    float* Ss   = Vs + 64 * 128;
    float* mrow = Ss + 64 * 64;
    float* lrow = mrow + 64;
    float* arow = lrow + 64;

    const int qt  = blockIdx.x;
    const int h   = blockIdx.y;
    const int m0  = qt * 64;
    const int kvh = h >> 2;
    const int tid = threadIdx.x;
    const int tx  = tid & 15;
    const int ty  = tid >> 4;
    const float scale = 0.08838834764831845f;

    #pragma unroll
    for (int t = 0; t < 8; ++t) {
        int linear = tid + t * 256;
        int r  = linear >> 5;
        int d4 = (linear & 31) * 4;
        float4 v = *(const float4*)&Q[(size_t)(m0 + r) * HID + h * HDIM + d4];
        Qs[(d4 + 0) * 64 + r] = v.x * scale;
        Qs[(d4 + 1) * 64 + r] = v.y * scale;
        Qs[(d4 + 2) * 64 + r] = v.z * scale;
        Qs[(d4 + 3) * 64 + r] = v.w * scale;
    }
    if (tid < 64) { mrow[tid] = -INFINITY; lrow[tid] = 0.f; }

    float acc[4][8];
    #pragma unroll
    for (int i = 0; i < 4; ++i)
        #pragma unroll
        for (int j = 0; j < 8; ++j) acc[i][j] = 0.f;

    const int j0 = (qt >= 16) ? qt - 16 : 0;
    for (int j = j0; j <= qt; ++j) {
        __syncthreads();

        #pragma unroll
        for (int t = 0; t < 8; ++t) {
            int linear = tid + t * 256;
            int r  = linear >> 5;
            int d4 = (linear & 31) * 4;
            size_t goff = (size_t)(j * 64 + r) * (NKV * HDIM) + kvh * HDIM + d4;
            float4 kv = *(const float4*)&K[goff];
            Ks[(d4 + 0) * 64 + r] = kv.x;
            Ks[(d4 + 1) * 64 + r] = kv.y;
            Ks[(d4 + 2) * 64 + r] = kv.z;
            Ks[(d4 + 3) * 64 + r] = kv.w;
            *(float4*)&Vs[r * 128 + d4] = *(const float4*)&V[goff];
        }
        __syncthreads();

        float s[4][4];
        #pragma unroll
        for (int i = 0; i < 4; ++i)
            #pragma unroll
            for (int jj = 0; jj < 4; ++jj) s[i][jj] = 0.f;

        for (int k = 0; k < 128; ++k) {
            float a[4], b[4];
            *(float4*)a = *(const float4*)&Qs[k * 64 + ty * 4];
            *(float4*)b = *(const float4*)&Ks[k * 64 + tx * 4];
            #pragma unroll
            for (int i = 0; i < 4; ++i)
                #pragma unroll
                for (int jj = 0; jj < 4; ++jj)
                    s[i][jj] += a[i] * b[jj];
        }

        #pragma unroll
        for (int i = 0; i < 4; ++i) {
            int qi = m0 + ty * 4 + i;
            #pragma unroll
            for (int jj = 0; jj < 4; ++jj) {
                int c = j * 64 + tx * 4 + jj;
                bool vis = (c <= qi) && (qi - c < WINDOW);
                Ss[(ty * 4 + i) * 64 + tx * 4 + jj] = vis ? s[i][jj] : -INFINITY;
            }
        }
        __syncthreads();

        {
            int r  = tid >> 2;
            int q4 = tid & 3;
            float vals[16];
            float tmax = -INFINITY;
            #pragma unroll
            for (int cidx = 0; cidx < 16; ++cidx) {
                vals[cidx] = Ss[r * 64 + q4 * 16 + cidx];
                tmax = fmaxf(tmax, vals[cidx]);
            }
            tmax = fmaxf(tmax, __shfl_xor_sync(0xffffffffu, tmax, 1));
            tmax = fmaxf(tmax, __shfl_xor_sync(0xffffffffu, tmax, 2));

            float mold = mrow[r];
            float mnew = fmaxf(mold, tmax);
            float alpha;
            float lsum = 0.f;
            if (mnew == -INFINITY) {
                alpha = 1.f;
                #pragma unroll
                for (int cidx = 0; cidx < 16; ++cidx)
                    Ss[r * 64 + q4 * 16 + cidx] = 0.f;
            } else {
                alpha = __expf(mold - mnew);
                #pragma unroll
                for (int cidx = 0; cidx < 16; ++cidx) {
                    float p = __expf(vals[cidx] - mnew);
                    Ss[r * 64 + q4 * 16 + cidx] = p;
                    lsum += p;
                }
            }
            lsum += __shfl_xor_sync(0xffffffffu, lsum, 1);
            lsum += __shfl_xor_sync(0xffffffffu, lsum, 2);
            if (q4 == 0) {
                mrow[r] = mnew;
                lrow[r] = lrow[r] * alpha + lsum;
                arow[r] = alpha;
            }
        }
        __syncthreads();

        #pragma unroll
        for (int i = 0; i < 4; ++i) {
            float al = arow[ty * 4 + i];
            #pragma unroll
            for (int jj = 0; jj < 8; ++jj) acc[i][jj] *= al;
        }
        for (int c = 0; c < 64; ++c) {
            float p[4], v[8];
            #pragma unroll
            for (int i = 0; i < 4; ++i) p[i] = Ss[(ty * 4 + i) * 64 + c];
            *(float4*)&v[0] = *(const float4*)&Vs[c * 128 + tx * 8];
            *(float4*)&v[4] = *(const float4*)&Vs[c * 128 + tx * 8 + 4];
            #pragma unroll
            for (int i = 0; i < 4; ++i)
                #pragma unroll
                for (int jj = 0; jj < 8; ++jj)
                    acc[i][jj] += p[i] * v[jj];
        }
    }

    #pragma unroll
    for (int i = 0; i < 4; ++i) {
        int r = ty * 4 + i;
        float inv = 1.f / lrow[r];
        float4 o0 = make_float4(acc[i][0] * inv, acc[i][1] * inv,
                                acc[i][2] * inv, acc[i][3] * inv);
        float4 o1 = make_float4(acc[i][4] * inv, acc[i][5] * inv,
                                acc[i][6] * inv, acc[i][7] * inv);
        float* op = &O[(size_t)(m0 + r) * HID + h * HDIM + tx * 8];
        *(float4*)&op[0] = o0;
        *(float4*)&op[4] = o1;
    }
}

// ---------------------------------------------------------------------------
extern "C" void kernel_launch(void* const* d_in, const int* in_sizes, int n_in,
                              void* d_out, int out_size)
{
    const float* hs  = (const float*)d_in[0];
    const int*   pos = (const int*)d_in[2];
    const float* Wq  = (const float*)d_in[3];
    const float* Wk  = (const float*)d_in[4];
    const float* Wv  = (const float*)d_in[5];
    const float* Wo  = (const float*)d_in[6];
    float* out = (float*)d_out;

    float *qb, *kb, *vb, *ab;
    cudaGetSymbolAddress((void**)&qb, g_Q);
    cudaGetSymbolAddress((void**)&kb, g_K);
    cudaGetSymbolAddress((void**)&vb, g_V);
    cudaGetSymbolAddress((void**)&ab, g_att);

    __nv_bfloat16 *hsh, *hsl, *ath, *atl, *wqh, *wql, *wkh, *wkl, *wvh, *wvl, *woh, *wol;
    cudaGetSymbolAddress((void**)&hsh, g_hs_hi);  cudaGetSymbolAddress((void**)&hsl, g_hs_lo);
    cudaGetSymbolAddress((void**)&ath, g_att_hi); cudaGetSymbolAddress((void**)&atl, g_att_lo);
    cudaGetSymbolAddress((void**)&wqh, g_Wq_hi);  cudaGetSymbolAddress((void**)&wql, g_Wq_lo);
    cudaGetSymbolAddress((void**)&wkh, g_Wk_hi);  cudaGetSymbolAddress((void**)&wkl, g_Wk_lo);
    cudaGetSymbolAddress((void**)&wvh, g_Wv_hi);  cudaGetSymbolAddress((void**)&wvl, g_Wv_lo);
    cudaGetSymbolAddress((void**)&woh, g_Wo_hi);  cudaGetSymbolAddress((void**)&wol, g_Wo_lo);

    const int gemm_smem = 1024 + 2 * BUFB;   // align pad + double buffer
    cudaFuncSetAttribute(gemm_bf16x3, cudaFuncAttributeMaxDynamicSharedMemorySize, gemm_smem);
    const int attn_smem = (128 * 64 * 2 + 64 * 128 + 64 * 64 + 3 * 64) * (int)sizeof(float);
    cudaFuncSetAttribute(attn_kernel, cudaFuncAttributeMaxDynamicSharedMemorySize, attn_smem);

    // split fp32 -> bf16 hi/lo
    {
        int n;
        n = S_LEN * HID / 4;        split_kernel<<<(n + 255) / 256, 256>>>(hs, hsh, hsl, n);
        n = HID * HID / 4;          split_kernel<<<(n + 255) / 256, 256>>>(Wq, wqh, wql, n);
        n = NKV * HDIM * HID / 4;   split_kernel<<<(n + 255) / 256, 256>>>(Wk, wkh, wkl, n);
        n = NKV * HDIM * HID / 4;   split_kernel<<<(n + 255) / 256, 256>>>(Wv, wvh, wvl, n);
        n = HID * HID / 4;          split_kernel<<<(n + 255) / 256, 256>>>(Wo, woh, wol, n);
    }

    // projections on tensor cores (mma.sync path)
    gemm_bf16x3<<<dim3(HID / 128, S_LEN / 128), 256, gemm_smem>>>(hsh, hsl, wqh, wql, qb, S_LEN, HID, KDIM);
    gemm_bf16x3<<<dim3(NKV * HDIM / 128, S_LEN / 128), 256, gemm_smem>>>(hsh, hsl, wkh, wkl, kb, S_LEN, NKV * HDIM, KDIM);
    gemm_bf16x3<<<dim3(NKV * HDIM / 128, S_LEN / 128), 256, gemm_smem>>>(hsh, hsl, wvh, wvl, vb, S_LEN, NKV * HDIM, KDIM);

    // RoPE
    {
        int totq = S_LEN * NH * 64;
        rope_kernel<<<(totq + 255) / 256, 256>>>(qb, pos, NH);
        int totk = S_LEN * NKV * 64;
        rope_kernel<<<(totk + 255) / 256, 256>>>(kb, pos, NKV);
    }

    // attention (fp32)
    attn_kernel<<<dim3(S_LEN / 64, NH), 256, attn_smem>>>(qb, kb, vb, ab);

    // split attention output, output projection
    {
        int n = S_LEN * HID / 4;
        split_kernel<<<(n + 255) / 256, 256>>>(ab, ath, atl, n);
    }
    gemm_bf16x3<<<dim3(HID / 128, S_LEN / 128), 256, gemm_smem>>>(ath, atl, woh, wol, out, S_LEN, HID, KDIM);
}

// round 7
// speedup vs baseline: 3.1579x; 1.6101x over previous
#include <cuda_runtime.h>
#include <cuda_bf16.h>
#include <math.h>
#include <stdint.h>

#define S_LEN 2048
#define HID   4096
#define NH    32
#define NKV   8
#define HDIM  128
#define WINDOW 1024
#define KDIM  4096

// ---------------- scratch (__device__ globals; no allocation) ----------------
__device__ float g_Q[S_LEN * HID];
__device__ float g_K[S_LEN * NKV * HDIM];
__device__ float g_V[S_LEN * NKV * HDIM];

__device__ __align__(256) __nv_bfloat16 g_hs_hi[S_LEN * HID];
__device__ __align__(256) __nv_bfloat16 g_hs_lo[S_LEN * HID];
__device__ __align__(256) __nv_bfloat16 g_att_hi[S_LEN * HID];
__device__ __align__(256) __nv_bfloat16 g_att_lo[S_LEN * HID];
__device__ __align__(256) __nv_bfloat16 g_Qh[S_LEN * HID];
__device__ __align__(256) __nv_bfloat16 g_Ql[S_LEN * HID];
__device__ __align__(256) __nv_bfloat16 g_Kh[S_LEN * NKV * HDIM];
__device__ __align__(256) __nv_bfloat16 g_Kl[S_LEN * NKV * HDIM];
__device__ __align__(256) __nv_bfloat16 g_Vh[S_LEN * NKV * HDIM];
__device__ __align__(256) __nv_bfloat16 g_Vl[S_LEN * NKV * HDIM];
__device__ __align__(256) __nv_bfloat16 g_Wq_hi[HID * HID];
__device__ __align__(256) __nv_bfloat16 g_Wq_lo[HID * HID];
__device__ __align__(256) __nv_bfloat16 g_Wk_hi[NKV * HDIM * HID];
__device__ __align__(256) __nv_bfloat16 g_Wk_lo[NKV * HDIM * HID];
__device__ __align__(256) __nv_bfloat16 g_Wv_hi[NKV * HDIM * HID];
__device__ __align__(256) __nv_bfloat16 g_Wv_lo[NKV * HDIM * HID];
__device__ __align__(256) __nv_bfloat16 g_Wo_hi[HID * HID];
__device__ __align__(256) __nv_bfloat16 g_Wo_lo[HID * HID];

// ---------------- helpers (baseline PTX only: sm_80-class features) ----------
__device__ __forceinline__ uint32_t smem_u32(const void* p) {
    uint32_t a;
    asm("{ .reg .u64 t; cvta.to.shared.u64 t, %1; cvt.u32.u64 %0, t; }" : "=r"(a) : "l"(p));
    return a;
}
__device__ __forceinline__ void cp16(uint32_t dst, const void* src) {
    asm volatile("cp.async.cg.shared.global [%0], [%1], 16;" :: "r"(dst), "l"(src));
}
__device__ __forceinline__ void cp_commit() {
    asm volatile("cp.async.commit_group;" ::: "memory");
}
template <int N>
__device__ __forceinline__ void cp_wait() {
    asm volatile("cp.async.wait_group %0;" :: "n"(N) : "memory");
}
__device__ __forceinline__ void ldsm_x4(uint32_t* r, uint32_t addr) {
    asm volatile("ldmatrix.sync.aligned.m8n8.x4.shared.b16 {%0,%1,%2,%3}, [%4];"
                 : "=r"(r[0]), "=r"(r[1]), "=r"(r[2]), "=r"(r[3]) : "r"(addr));
}
__device__ __forceinline__ void ldsm_x4_t(uint32_t* r, uint32_t addr) {
    asm volatile("ldmatrix.sync.aligned.m8n8.x4.trans.shared.b16 {%0,%1,%2,%3}, [%4];"
                 : "=r"(r[0]), "=r"(r[1]), "=r"(r[2]), "=r"(r[3]) : "r"(addr));
}
__device__ __forceinline__ void mma16816(float* c, const uint32_t* a,
                                         uint32_t b0, uint32_t b1) {
    asm volatile(
        "mma.sync.aligned.m16n8k16.row.col.f32.bf16.bf16.f32 "
        "{%0,%1,%2,%3}, {%4,%5,%6,%7}, {%8,%9}, {%0,%1,%2,%3};"
        : "+f"(c[0]), "+f"(c[1]), "+f"(c[2]), "+f"(c[3])
        : "r"(a[0]), "r"(a[1]), "r"(a[2]), "r"(a[3]), "r"(b0), "r"(b1));
}
__device__ __forceinline__ void packsplit(float x, float y, uint32_t& hi, uint32_t& lo) {
    __nv_bfloat16 hx = __float2bfloat16(x), hy = __float2bfloat16(y);
    __nv_bfloat16 lx = __float2bfloat16(x - __bfloat162float(hx));
    __nv_bfloat16 ly = __float2bfloat16(y - __bfloat162float(hy));
    hi = (uint32_t)__bfloat16_as_ushort(hx) | ((uint32_t)__bfloat16_as_ushort(hy) << 16);
    lo = (uint32_t)__bfloat16_as_ushort(lx) | ((uint32_t)__bfloat16_as_ushort(ly) << 16);
}

#define SWZ(off) ((off) ^ (((off) >> 3) & 0x70))

// ---------------------------------------------------------------------------
// split fp32 -> bf16 hi + bf16 lo (residual)
// ---------------------------------------------------------------------------
__global__ void split_kernel(const float* __restrict__ in,
                             __nv_bfloat16* __restrict__ hi,
                             __nv_bfloat16* __restrict__ lo, int n4)
{
    int i = blockIdx.x * blockDim.x + threadIdx.x;
    if (i >= n4) return;
    float4 v = ((const float4*)in)[i];
    float x[4] = {v.x, v.y, v.z, v.w};
    unsigned short h[4], l[4];
    #pragma unroll
    for (int j = 0; j < 4; ++j) {
        __nv_bfloat16 hb = __float2bfloat16(x[j]);
        __nv_bfloat16 lb = __float2bfloat16(x[j] - __bfloat162float(hb));
        h[j] = __bfloat16_as_ushort(hb);
        l[j] = __bfloat16_as_ushort(lb);
    }
    ((ushort4*)hi)[i] = make_ushort4(h[0], h[1], h[2], h[3]);
    ((ushort4*)lo)[i] = make_ushort4(l[0], l[1], l[2], l[3]);
}

// ---------------------------------------------------------------------------
// GEMM: C[M][N] = (Ahi+Alo)*(Bhi+Blo)^T via mma.sync bf16x3 (unchanged from R6)
// ---------------------------------------------------------------------------
#define GK 64
#define TILEB 16384
#define BUFB (4 * TILEB)

__global__ void __launch_bounds__(256, 1)
gemm_bf16x3(const __nv_bfloat16* __restrict__ Ahi, const __nv_bfloat16* __restrict__ Alo,
            const __nv_bfloat16* __restrict__ Bhi, const __nv_bfloat16* __restrict__ Blo,
            float* __restrict__ C, int M, int N, int K)
{
    extern __shared__ char smraw[];
    char* smc = (char*)(((uintptr_t)smraw + 1023) & ~(uintptr_t)1023);
    const uint32_t sbase = smem_u32(smc);

    const int tid = threadIdx.x;
    const int lane = tid & 31;
    const int wid = tid >> 5;
    const int wr = wid >> 2;
    const int wc = wid & 3;
    const int m0 = blockIdx.y * 128;
    const int n0 = blockIdx.x * 128;

    float acc[4][4][4];
    #pragma unroll
    for (int a = 0; a < 4; ++a)
        #pragma unroll
        for (int b = 0; b < 4; ++b)
            #pragma unroll
            for (int c = 0; c < 4; ++c) acc[a][b][c] = 0.f;

    const int NCHUNK = K / GK;

    auto load_chunk = [&](int it) {
        const uint32_t bufb = sbase + (it & 1) * BUFB;
        const int k0 = it * GK;
        #pragma unroll
        for (int p = 0; p < 4; ++p) {
            int linear = tid + p * 256;
            int r = linear >> 3;
            int cb = (linear & 7) * 16;
            uint32_t sw = SWZ((uint32_t)(r * 128 + cb));
            size_t ga = (size_t)(m0 + r) * K + k0 + (cb >> 1);
            size_t gb = (size_t)(n0 + r) * K + k0 + (cb >> 1);
            cp16(bufb + sw,              &Ahi[ga]);
            cp16(bufb + TILEB + sw,      &Alo[ga]);
            cp16(bufb + 2 * TILEB + sw,  &Bhi[gb]);
            cp16(bufb + 3 * TILEB + sw,  &Blo[gb]);
        }
    };

    load_chunk(0);
    cp_commit();

    const int lrow = lane & 15;
    const int lkb  = (lane >> 4) * 16;

    for (int it = 0; it < NCHUNK; ++it) {
        if (it + 1 < NCHUNK) {
            load_chunk(it + 1);
            cp_commit();
            cp_wait<1>();
        } else {
            cp_wait<0>();
        }
        __syncthreads();

        const uint32_t bufb = sbase + (it & 1) * BUFB;

        #pragma unroll
        for (int ks = 0; ks < 4; ++ks) {
            uint32_t ah[4][4], al[4][4], bh[2][4], bl[2][4];
            #pragma unroll
            for (int mi = 0; mi < 4; ++mi) {
                uint32_t off = (uint32_t)((wr * 64 + mi * 16 + lrow) * 128 + ks * 32 + lkb);
                uint32_t sw = SWZ(off);
                ldsm_x4(ah[mi], bufb + sw);
                ldsm_x4(al[mi], bufb + TILEB + sw);
            }
            #pragma unroll
            for (int np = 0; np < 2; ++np) {
                uint32_t off = (uint32_t)((wc * 32 + np * 16 + lrow) * 128 + ks * 32 + lkb);
                uint32_t sw = SWZ(off);
                ldsm_x4(bh[np], bufb + 2 * TILEB + sw);
                ldsm_x4(bl[np], bufb + 3 * TILEB + sw);
            }
            #pragma unroll
            for (int mi = 0; mi < 4; ++mi)
                #pragma unroll
                for (int ni = 0; ni < 4; ++ni) {
                    uint32_t b0h = bh[ni >> 1][ni & 1], b1h = bh[ni >> 1][2 + (ni & 1)];
                    uint32_t b0l = bl[ni >> 1][ni & 1], b1l = bl[ni >> 1][2 + (ni & 1)];
                    mma16816(acc[mi][ni], ah[mi], b0h, b1h);
                    mma16816(acc[mi][ni], ah[mi], b0l, b1l);
                    mma16816(acc[mi][ni], al[mi], b0h, b1h);
                }
        }
        __syncthreads();
    }

    const int row_base = m0 + wr * 64 + (lane >> 2);
    const int col_base = n0 + wc * 32 + (lane & 3) * 2;
    #pragma unroll
    for (int mi = 0; mi < 4; ++mi)
        #pragma unroll
        for (int ni = 0; ni < 4; ++ni) {
            int r = row_base + mi * 16;
            int cc = col_base + ni * 8;
            *(float2*)&C[(size_t)r * N + cc]       = make_float2(acc[mi][ni][0], acc[mi][ni][1]);
            *(float2*)&C[(size_t)(r + 8) * N + cc] = make_float2(acc[mi][ni][2], acc[mi][ni][3]);
        }
}

// ---------------------------------------------------------------------------
// RoPE in place on X[token][h*128 + d], pair (d, d+64), d<64.
// ---------------------------------------------------------------------------
__global__ void rope_kernel(float* __restrict__ X, const int* __restrict__ pos_ids,
                            int nheads)
{
    int idx = blockIdx.x * blockDim.x + threadIdx.x;
    int total = S_LEN * nheads * 64;
    if (idx >= total) return;
    int d = idx % 64;
    int h = (idx / 64) % nheads;
    int t = idx / (64 * nheads);

    float invf = expf(-(float)d * 0.14391156831212787f);
    float ang = (float)pos_ids[t] * invf;
    float s, c;
    sincosf(ang, &s, &c);

    float* base = X + (size_t)t * nheads * HDIM + h * HDIM;
    float x0 = base[d];
    float x1 = base[d + 64];
    base[d]      = x0 * c - x1 * s;
    base[d + 64] = x1 * c + x0 * s;
}

// ---------------------------------------------------------------------------
// Flash attention on tensor cores (bf16x3, online softmax in registers).
// CTA = (128 q rows, head). 8 warps x 16 rows. cp.async double-buffered K/V.
// SMEM: Q 4x16KB | KV buf0 4x16KB | KV buf1 4x16KB   (192 KB + align pad)
// ---------------------------------------------------------------------------
#define ATT_SMEM (1024 + 3 * 65536)

__global__ void __launch_bounds__(256)
attn_mma(const __nv_bfloat16* __restrict__ Qh_g, const __nv_bfloat16* __restrict__ Ql_g,
         const __nv_bfloat16* __restrict__ Kh_g, const __nv_bfloat16* __restrict__ Kl_g,
         const __nv_bfloat16* __restrict__ Vh_g, const __nv_bfloat16* __restrict__ Vl_g,
         __nv_bfloat16* __restrict__ Oh_g, __nv_bfloat16* __restrict__ Ol_g)
{
    extern __shared__ char smraw[];
    char* smc = (char*)(((uintptr_t)smraw + 1023) & ~(uintptr_t)1023);
    const uint32_t qbase = smem_u32(smc);
    const uint32_t kvbase = qbase + 65536;

    const int tid = threadIdx.x;
    const int lane = tid & 31;
    const int w = tid >> 5;
    const int wm = w * 16;
    const int m0 = blockIdx.x * 128;
    const int h = blockIdx.y;
    const int kvh = h >> 2;
    const int lrow = lane & 15;
    const int lhi = (lane >> 4) * 16;

    // ---- loaders ----
    auto load_q = [&]() {
        #pragma unroll
        for (int p = 0; p < 16; ++p) {
            int lin = tid + p * 256;
            int t2 = lin >> 11;                 // 0 hi, 1 lo
            int rem = lin & 2047;
            int row = rem >> 4;
            int c = rem & 15;
            int half = c >> 3;
            int cb = (c & 7) * 16;
            uint32_t dst = qbase + t2 * 32768 + half * 16384
                         + SWZ((uint32_t)(row * 128 + cb));
            size_t elem = (size_t)(m0 + row) * HID + h * HDIM + half * 64 + (c & 7) * 8;
            cp16(dst, (t2 ? Ql_g : Qh_g) + elem);
        }
    };
    auto load_kv = [&](int j, int b) {
        const uint32_t base = kvbase + b * 65536;
        #pragma unroll
        for (int p = 0; p < 16; ++p) {
            int lin = tid + p * 256;
            int t4 = lin >> 10;                 // 0 Kh, 1 Kl, 2 Vh, 3 Vl
            int rem = lin & 1023;
            int row = rem >> 4;
            int c = rem & 15;
            int half = c >> 3;
            int cb = (c & 7) * 16;
            uint32_t dst = base + t4 * 16384 + half * 8192
                         + SWZ((uint32_t)(row * 128 + cb));
            size_t elem = (size_t)(j * 64 + row) * (NKV * HDIM) + kvh * HDIM
                        + half * 64 + (c & 7) * 8;
            const __nv_bfloat16* src =
                (t4 < 2) ? ((t4 & 1) ? Kl_g : Kh_g) : ((t4 & 1) ? Vl_g : Vh_g);
            cp16(dst, src + elem);
        }
    };

    const int j0 = (m0 >= 1024) ? (m0 - 1023) / 64 : 0;
    const int jend = m0 / 64 + 1;

    load_q();
    load_kv(j0, 0);
    cp_commit();

    // ---- register state ----
    float o[16][4];
    #pragma unroll
    for (int i = 0; i < 16; ++i)
        #pragma unroll
        for (int c = 0; c < 4; ++c) o[i][c] = 0.f;
    float mst0 = -INFINITY, mst1 = -INFINITY, lst0 = 0.f, lst1 = 0.f;

    const int row0 = m0 + wm + (lane >> 2);
    const int row1 = row0 + 8;
    const float scale = 0.08838834764831845f;

    for (int j = j0; j <= jend; ++j) {
        const int b = (j - j0) & 1;
        if (j + 1 <= jend) {
            load_kv(j + 1, b ^ 1);
            cp_commit();
            cp_wait<1>();
        } else {
            cp_wait<0>();
        }
        __syncthreads();

        const uint32_t kvb = kvbase + b * 65536;

        // ---- S = Q K^T (bf16x3) ----
        float sf[8][4];
        #pragma unroll
        for (int i = 0; i < 8; ++i)
            #pragma unroll
            for (int c = 0; c < 4; ++c) sf[i][c] = 0.f;

        #pragma unroll
        for (int kd = 0; kd < 8; ++kd) {
            const int half = kd >> 2;
            const uint32_t koff = (uint32_t)((kd & 3) * 32 + lhi);
            uint32_t ah[4], al[4], bh[4][4], bl[4][4];
            {
                uint32_t sw = SWZ((uint32_t)((wm + lrow) * 128) + koff);
                ldsm_x4(ah, qbase + half * 16384 + sw);
                ldsm_x4(al, qbase + 32768 + half * 16384 + sw);
            }
            #pragma unroll
            for (int nb = 0; nb < 4; ++nb) {
                uint32_t sw = SWZ((uint32_t)((nb * 16 + lrow) * 128) + koff);
                ldsm_x4(bh[nb], kvb + half * 8192 + sw);
                ldsm_x4(bl[nb], kvb + 16384 + half * 8192 + sw);
            }
            #pragma unroll
            for (int ni = 0; ni < 8; ++ni) {
                const int nb = ni >> 1, s = ni & 1;
                mma16816(sf[ni], ah, bh[nb][s], bh[nb][s + 2]);
                mma16816(sf[ni], ah, bl[nb][s], bl[nb][s + 2]);
                mma16816(sf[ni], al, bh[nb][s], bh[nb][s + 2]);
            }
        }

        // ---- scale + mask + online softmax ----
        const int colb = j * 64 + (lane & 3) * 2;
        float rmax0 = -INFINITY, rmax1 = -INFINITY;
        #pragma unroll
        for (int ni = 0; ni < 8; ++ni) {
            int c0 = colb + ni * 8, c1 = c0 + 1;
            sf[ni][0] = (c0 <= row0 && row0 - c0 < WINDOW) ? sf[ni][0] * scale : -INFINITY;
            sf[ni][1] = (c1 <= row0 && row0 - c1 < WINDOW) ? sf[ni][1] * scale : -INFINITY;
            sf[ni][2] = (c0 <= row1 && row1 - c0 < WINDOW) ? sf[ni][2] * scale : -INFINITY;
            sf[ni][3] = (c1 <= row1 && row1 - c1 < WINDOW) ? sf[ni][3] * scale : -INFINITY;
            rmax0 = fmaxf(rmax0, fmaxf(sf[ni][0], sf[ni][1]));
            rmax1 = fmaxf(rmax1, fmaxf(sf[ni][2], sf[ni][3]));
        }
        rmax0 = fmaxf(rmax0, __shfl_xor_sync(0xffffffffu, rmax0, 1));
        rmax0 = fmaxf(rmax0, __shfl_xor_sync(0xffffffffu, rmax0, 2));
        rmax1 = fmaxf(rmax1, __shfl_xor_sync(0xffffffffu, rmax1, 1));
        rmax1 = fmaxf(rmax1, __shfl_xor_sync(0xffffffffu, rmax1, 2));

        float mn0 = fmaxf(mst0, rmax0), mn1 = fmaxf(mst1, rmax1);
        float mc0 = fmaxf(mn0, -1e30f), mc1 = fmaxf(mn1, -1e30f);
        float a0 = __expf(fmaxf(mst0, -1e30f) - mc0);
        float a1 = __expf(fmaxf(mst1, -1e30f) - mc1);
        float sum0 = 0.f, sum1 = 0.f;
        #pragma unroll
        for (int ni = 0; ni < 8; ++ni) {
            sf[ni][0] = __expf(sf[ni][0] - mc0);
            sf[ni][1] = __expf(sf[ni][1] - mc0);
            sf[ni][2] = __expf(sf[ni][2] - mc1);
            sf[ni][3] = __expf(sf[ni][3] - mc1);
            sum0 += sf[ni][0] + sf[ni][1];
            sum1 += sf[ni][2] + sf[ni][3];
        }
        sum0 += __shfl_xor_sync(0xffffffffu, sum0, 1);
        sum0 += __shfl_xor_sync(0xffffffffu, sum0, 2);
        sum1 += __shfl_xor_sync(0xffffffffu, sum1, 1);
        sum1 += __shfl_xor_sync(0xffffffffu, sum1, 2);
        mst0 = mn0; mst1 = mn1;
        lst0 = lst0 * a0 + sum0;
        lst1 = lst1 * a1 + sum1;
        #pragma unroll
        for (int nf = 0; nf < 16; ++nf) {
            o[nf][0] *= a0; o[nf][1] *= a0;
            o[nf][2] *= a1; o[nf][3] *= a1;
        }

        // ---- O += P V (bf16x3), P from registers ----
        #pragma unroll
        for (int ks = 0; ks < 4; ++ks) {
            uint32_t ah[4], al[4];
            packsplit(sf[2 * ks][0],     sf[2 * ks][1],     ah[0], al[0]);
            packsplit(sf[2 * ks][2],     sf[2 * ks][3],     ah[1], al[1]);
            packsplit(sf[2 * ks + 1][0], sf[2 * ks + 1][1], ah[2], al[2]);
            packsplit(sf[2 * ks + 1][2], sf[2 * ks + 1][3], ah[3], al[3]);
            #pragma unroll
            for (int g = 0; g < 8; ++g) {
                const int half = g >> 2;
                uint32_t off = SWZ((uint32_t)((ks * 16 + lrow) * 128 + (g & 3) * 32) + lhi);
                uint32_t vh[4], vl[4];
                ldsm_x4_t(vh, kvb + 32768 + half * 8192 + off);
                ldsm_x4_t(vl, kvb + 49152 + half * 8192 + off);
                mma16816(o[2 * g],     ah, vh[0], vh[1]);
                mma16816(o[2 * g],     ah, vl[0], vl[1]);
                mma16816(o[2 * g],     al, vh[0], vh[1]);
                mma16816(o[2 * g + 1], ah, vh[2], vh[3]);
                mma16816(o[2 * g + 1], ah, vl[2], vl[3]);
                mma16816(o[2 * g + 1], al, vh[2], vh[3]);
            }
        }
        __syncthreads();
    }

    // ---- epilogue: normalize, split to bf16 hi/lo, store ----
    const float inv0 = 1.f / lst0;
    const float inv1 = 1.f / lst1;
    #pragma unroll
    for (int nf = 0; nf < 16; ++nf) {
        int d = h * HDIM + nf * 8 + (lane & 3) * 2;
        size_t off0 = (size_t)row0 * HID + d;
        size_t off1 = (size_t)row1 * HID + d;
        uint32_t hi, lo;
        packsplit(o[nf][0] * inv0, o[nf][1] * inv0, hi, lo);
        *(uint32_t*)(Oh_g + off0) = hi;
        *(uint32_t*)(Ol_g + off0) = lo;
        packsplit(o[nf][2] * inv1, o[nf][3] * inv1, hi, lo);
        *(uint32_t*)(Oh_g + off1) = hi;
        *(uint32_t*)(Ol_g + off1) = lo;
    }
}

// ---------------------------------------------------------------------------
extern "C" void kernel_launch(void* const* d_in, const int* in_sizes, int n_in,
                              void* d_out, int out_size)
{
    const float* hs  = (const float*)d_in[0];
    const int*   pos = (const int*)d_in[2];
    const float* Wq  = (const float*)d_in[3];
    const float* Wk  = (const float*)d_in[4];
    const float* Wv  = (const float*)d_in[5];
    const float* Wo  = (const float*)d_in[6];
    float* out = (float*)d_out;

    float *qb, *kb, *vb;
    cudaGetSymbolAddress((void**)&qb, g_Q);
    cudaGetSymbolAddress((void**)&kb, g_K);
    cudaGetSymbolAddress((void**)&vb, g_V);

    __nv_bfloat16 *hsh, *hsl, *ath, *atl, *wqh, *wql, *wkh, *wkl, *wvh, *wvl, *woh, *wol;
    __nv_bfloat16 *qhh, *qll, *khh, *kll, *vhh, *vll;
    cudaGetSymbolAddress((void**)&hsh, g_hs_hi);  cudaGetSymbolAddress((void**)&hsl, g_hs_lo);
    cudaGetSymbolAddress((void**)&ath, g_att_hi); cudaGetSymbolAddress((void**)&atl, g_att_lo);
    cudaGetSymbolAddress((void**)&wqh, g_Wq_hi);  cudaGetSymbolAddress((void**)&wql, g_Wq_lo);
    cudaGetSymbolAddress((void**)&wkh, g_Wk_hi);  cudaGetSymbolAddress((void**)&wkl, g_Wk_lo);
    cudaGetSymbolAddress((void**)&wvh, g_Wv_hi);  cudaGetSymbolAddress((void**)&wvl, g_Wv_lo);
    cudaGetSymbolAddress((void**)&woh, g_Wo_hi);  cudaGetSymbolAddress((void**)&wol, g_Wo_lo);
    cudaGetSymbolAddress((void**)&qhh, g_Qh);     cudaGetSymbolAddress((void**)&qll, g_Ql);
    cudaGetSymbolAddress((void**)&khh, g_Kh);     cudaGetSymbolAddress((void**)&kll, g_Kl);
    cudaGetSymbolAddress((void**)&vhh, g_Vh);     cudaGetSymbolAddress((void**)&vll, g_Vl);

    const int gemm_smem = 1024 + 2 * BUFB;
    cudaFuncSetAttribute(gemm_bf16x3, cudaFuncAttributeMaxDynamicSharedMemorySize, gemm_smem);
    cudaFuncSetAttribute(attn_mma, cudaFuncAttributeMaxDynamicSharedMemorySize, ATT_SMEM);

    // split fp32 inputs -> bf16 hi/lo
    {
        int n;
        n = S_LEN * HID / 4;        split_kernel<<<(n + 255) / 256, 256>>>(hs, hsh, hsl, n);
        n = HID * HID / 4;          split_kernel<<<(n + 255) / 256, 256>>>(Wq, wqh, wql, n);
        n = NKV * HDIM * HID / 4;   split_kernel<<<(n + 255) / 256, 256>>>(Wk, wkh, wkl, n);
        n = NKV * HDIM * HID / 4;   split_kernel<<<(n + 255) / 256, 256>>>(Wv, wvh, wvl, n);
        n = HID * HID / 4;          split_kernel<<<(n + 255) / 256, 256>>>(Wo, woh, wol, n);
    }

    // projections (tensor cores)
    gemm_bf16x3<<<dim3(HID / 128, S_LEN / 128), 256, gemm_smem>>>(hsh, hsl, wqh, wql, qb, S_LEN, HID, KDIM);
    gemm_bf16x3<<<dim3(NKV * HDIM / 128, S_LEN / 128), 256, gemm_smem>>>(hsh, hsl, wkh, wkl, kb, S_LEN, NKV * HDIM, KDIM);
    gemm_bf16x3<<<dim3(NKV * HDIM / 128, S_LEN / 128), 256, gemm_smem>>>(hsh, hsl, wvh, wvl, vb, S_LEN, NKV * HDIM, KDIM);

    // RoPE (fp32, in place)
    {
        int totq = S_LEN * NH * 64;
        rope_kernel<<<(totq + 255) / 256, 256>>>(qb, pos, NH);
        int totk = S_LEN * NKV * 64;
        rope_kernel<<<(totk + 255) / 256, 256>>>(kb, pos, NKV);
    }

    // split Q/K/V for tensor-core attention
    {
        int n;
        n = S_LEN * HID / 4;            split_kernel<<<(n + 255) / 256, 256>>>(qb, qhh, qll, n);
        n = S_LEN * NKV * HDIM / 4;     split_kernel<<<(n + 255) / 256, 256>>>(kb, khh, kll, n);
        n = S_LEN * NKV * HDIM / 4;     split_kernel<<<(n + 255) / 256, 256>>>(vb, vhh, vll, n);
    }

    // attention (tensor cores), writes bf16 hi/lo directly
    attn_mma<<<dim3(S_LEN / 128, NH), 256, ATT_SMEM>>>(qhh, qll, khh, kll, vhh, vll, ath, atl);

    // output projection
    gemm_bf16x3<<<dim3(HID / 128, S_LEN / 128), 256, gemm_smem>>>(ath, atl, woh, wol, out, S_LEN, HID, KDIM);
}

// round 8
// speedup vs baseline: 3.1956x; 1.0119x over previous
#include <cuda_runtime.h>
#include <cuda_bf16.h>
#include <math.h>
#include <stdint.h>

#define S_LEN 2048
#define HID   4096
#define NH    32
#define NKV   8
#define HDIM  128
#define WINDOW 1024
#define KDIM  4096
#define NKVD  (NKV * HDIM)      // 1024

// ---------------- scratch (__device__ globals; no allocation) ----------------
__device__ __align__(256) __nv_bfloat16 g_hs_hi[S_LEN * HID];
__device__ __align__(256) __nv_bfloat16 g_hs_lo[S_LEN * HID];
__device__ __align__(256) __nv_bfloat16 g_att_hi[S_LEN * HID];
__device__ __align__(256) __nv_bfloat16 g_att_lo[S_LEN * HID];
__device__ __align__(256) __nv_bfloat16 g_Qh[S_LEN * HID];
__device__ __align__(256) __nv_bfloat16 g_Ql[S_LEN * HID];
__device__ __align__(256) __nv_bfloat16 g_Kh[S_LEN * NKVD];
__device__ __align__(256) __nv_bfloat16 g_Kl[S_LEN * NKVD];
__device__ __align__(256) __nv_bfloat16 g_Vh[S_LEN * NKVD];
__device__ __align__(256) __nv_bfloat16 g_Vl[S_LEN * NKVD];
__device__ __align__(256) __nv_bfloat16 g_Wq_hi[HID * HID];
__device__ __align__(256) __nv_bfloat16 g_Wq_lo[HID * HID];
__device__ __align__(256) __nv_bfloat16 g_Wk_hi[NKVD * HID];
__device__ __align__(256) __nv_bfloat16 g_Wk_lo[NKVD * HID];
__device__ __align__(256) __nv_bfloat16 g_Wv_hi[NKVD * HID];
__device__ __align__(256) __nv_bfloat16 g_Wv_lo[NKVD * HID];
__device__ __align__(256) __nv_bfloat16 g_Wo_hi[HID * HID];
__device__ __align__(256) __nv_bfloat16 g_Wo_lo[HID * HID];

// ---------------- helpers (baseline PTX only: sm_80-class features) ----------
__device__ __forceinline__ uint32_t smem_u32(const void* p) {
    uint32_t a;
    asm("{ .reg .u64 t; cvta.to.shared.u64 t, %1; cvt.u32.u64 %0, t; }" : "=r"(a) : "l"(p));
    return a;
}
__device__ __forceinline__ void cp16(uint32_t dst, const void* src) {
    asm volatile("cp.async.cg.shared.global [%0], [%1], 16;" :: "r"(dst), "l"(src));
}
__device__ __forceinline__ void cp_commit() {
    asm volatile("cp.async.commit_group;" ::: "memory");
}
template <int N>
__device__ __forceinline__ void cp_wait() {
    asm volatile("cp.async.wait_group %0;" :: "n"(N) : "memory");
}
__device__ __forceinline__ void ldsm_x4(uint32_t* r, uint32_t addr) {
    asm volatile("ldmatrix.sync.aligned.m8n8.x4.shared.b16 {%0,%1,%2,%3}, [%4];"
                 : "=r"(r[0]), "=r"(r[1]), "=r"(r[2]), "=r"(r[3]) : "r"(addr));
}
__device__ __forceinline__ void ldsm_x4_t(uint32_t* r, uint32_t addr) {
    asm volatile("ldmatrix.sync.aligned.m8n8.x4.trans.shared.b16 {%0,%1,%2,%3}, [%4];"
                 : "=r"(r[0]), "=r"(r[1]), "=r"(r[2]), "=r"(r[3]) : "r"(addr));
}
__device__ __forceinline__ void mma16816(float* c, const uint32_t* a,
                                         uint32_t b0, uint32_t b1) {
    asm volatile(
        "mma.sync.aligned.m16n8k16.row.col.f32.bf16.bf16.f32 "
        "{%0,%1,%2,%3}, {%4,%5,%6,%7}, {%8,%9}, {%0,%1,%2,%3};"
        : "+f"(c[0]), "+f"(c[1]), "+f"(c[2]), "+f"(c[3])
        : "r"(a[0]), "r"(a[1]), "r"(a[2]), "r"(a[3]), "r"(b0), "r"(b1));
}
__device__ __forceinline__ void packsplit(float x, float y, uint32_t& hi, uint32_t& lo) {
    __nv_bfloat16 hx = __float2bfloat16(x), hy = __float2bfloat16(y);
    __nv_bfloat16 lx = __float2bfloat16(x - __bfloat162float(hx));
    __nv_bfloat16 ly = __float2bfloat16(y - __bfloat162float(hy));
    hi = (uint32_t)__bfloat16_as_ushort(hx) | ((uint32_t)__bfloat16_as_ushort(hy) << 16);
    lo = (uint32_t)__bfloat16_as_ushort(lx) | ((uint32_t)__bfloat16_as_ushort(ly) << 16);
}

#define SWZ(off) ((off) ^ (((off) >> 3) & 0x70))

// ---------------------------------------------------------------------------
// split fp32 -> bf16 hi + bf16 lo (residual)
// ---------------------------------------------------------------------------
__global__ void split_kernel(const float* __restrict__ in,
                             __nv_bfloat16* __restrict__ hi,
                             __nv_bfloat16* __restrict__ lo, int n4)
{
    int i = blockIdx.x * blockDim.x + threadIdx.x;
    if (i >= n4) return;
    float4 v = ((const float4*)in)[i];
    float x[4] = {v.x, v.y, v.z, v.w};
    unsigned short h[4], l[4];
    #pragma unroll
    for (int j = 0; j < 4; ++j) {
        __nv_bfloat16 hb = __float2bfloat16(x[j]);
        __nv_bfloat16 lb = __float2bfloat16(x[j] - __bfloat162float(hb));
        h[j] = __bfloat16_as_ushort(hb);
        l[j] = __bfloat16_as_ushort(lb);
    }
    ((ushort4*)hi)[i] = make_ushort4(h[0], h[1], h[2], h[3]);
    ((ushort4*)lo)[i] = make_ushort4(l[0], l[1], l[2], l[3]);
}

// ---------------------------------------------------------------------------
// Shared GEMM mainloop macro-structure constants
// ---------------------------------------------------------------------------
#define GK 64
#define TILEB 16384
#define BUFB (4 * TILEB)

// ---------------------------------------------------------------------------
// Fused QKV projection:  [Q|K|V] = hs @ [Wq|Wk|Wv]^T, RoPE on Q/K, split to
// bf16 hi/lo in the epilogue. Logical N = 6144, grid.x = 48.
// ---------------------------------------------------------------------------
__global__ void __launch_bounds__(256, 1)
gemm_qkv(const __nv_bfloat16* __restrict__ Ahi, const __nv_bfloat16* __restrict__ Alo,
         const int* __restrict__ pos,
         __nv_bfloat16* __restrict__ Qh, __nv_bfloat16* __restrict__ Ql,
         __nv_bfloat16* __restrict__ Kh, __nv_bfloat16* __restrict__ Kl,
         __nv_bfloat16* __restrict__ Vh, __nv_bfloat16* __restrict__ Vl)
{
    extern __shared__ char smraw[];
    char* smc = (char*)(((uintptr_t)smraw + 1023) & ~(uintptr_t)1023);
    const uint32_t sbase = smem_u32(smc);

    const int tid = threadIdx.x;
    const int lane = tid & 31;
    const int wid = tid >> 5;
    const int wr = wid >> 2;
    const int wc = wid & 3;
    const int bx = blockIdx.x;
    const int m0 = blockIdx.y * 128;

    // region select: 0..31 Q, 32..39 K, 40..47 V
    const __nv_bfloat16 *Bhi, *Blo;
    int bn0;
    if (bx < 32)      { Bhi = g_Wq_hi; Blo = g_Wq_lo; bn0 = bx * 128; }
    else if (bx < 40) { Bhi = g_Wk_hi; Blo = g_Wk_lo; bn0 = (bx - 32) * 128; }
    else              { Bhi = g_Wv_hi; Blo = g_Wv_lo; bn0 = (bx - 40) * 128; }

    float acc[4][4][4];
    #pragma unroll
    for (int a = 0; a < 4; ++a)
        #pragma unroll
        for (int b = 0; b < 4; ++b)
            #pragma unroll
            for (int c = 0; c < 4; ++c) acc[a][b][c] = 0.f;

    const int NCHUNK = KDIM / GK;

    auto load_chunk = [&](int it) {
        const uint32_t bufb = sbase + (it & 1) * BUFB;
        const int k0 = it * GK;
        #pragma unroll
        for (int p = 0; p < 4; ++p) {
            int linear = tid + p * 256;
            int r = linear >> 3;
            int cb = (linear & 7) * 16;
            uint32_t sw = SWZ((uint32_t)(r * 128 + cb));
            size_t ga = (size_t)(m0 + r) * KDIM + k0 + (cb >> 1);
            size_t gb = (size_t)(bn0 + r) * KDIM + k0 + (cb >> 1);
            cp16(bufb + sw,              &Ahi[ga]);
            cp16(bufb + TILEB + sw,      &Alo[ga]);
            cp16(bufb + 2 * TILEB + sw,  &Bhi[gb]);
            cp16(bufb + 3 * TILEB + sw,  &Blo[gb]);
        }
    };

    load_chunk(0);
    cp_commit();

    const int lrow = lane & 15;
    const int lkb  = (lane >> 4) * 16;

    for (int it = 0; it < NCHUNK; ++it) {
        if (it + 1 < NCHUNK) {
            load_chunk(it + 1);
            cp_commit();
            cp_wait<1>();
        } else {
            cp_wait<0>();
        }
        __syncthreads();

        const uint32_t bufb = sbase + (it & 1) * BUFB;

        #pragma unroll
        for (int ks = 0; ks < 4; ++ks) {
            uint32_t ah[4][4], al[4][4], bh[2][4], bl[2][4];
            #pragma unroll
            for (int mi = 0; mi < 4; ++mi) {
                uint32_t off = (uint32_t)((wr * 64 + mi * 16 + lrow) * 128 + ks * 32 + lkb);
                uint32_t sw = SWZ(off);
                ldsm_x4(ah[mi], bufb + sw);
                ldsm_x4(al[mi], bufb + TILEB + sw);
            }
            #pragma unroll
            for (int np = 0; np < 2; ++np) {
                uint32_t off = (uint32_t)((wc * 32 + np * 16 + lrow) * 128 + ks * 32 + lkb);
                uint32_t sw = SWZ(off);
                ldsm_x4(bh[np], bufb + 2 * TILEB + sw);
                ldsm_x4(bl[np], bufb + 3 * TILEB + sw);
            }
            #pragma unroll
            for (int mi = 0; mi < 4; ++mi)
                #pragma unroll
                for (int ni = 0; ni < 4; ++ni) {
                    uint32_t b0h = bh[ni >> 1][ni & 1], b1h = bh[ni >> 1][2 + (ni & 1)];
                    uint32_t b0l = bl[ni >> 1][ni & 1], b1l = bl[ni >> 1][2 + (ni & 1)];
                    mma16816(acc[mi][ni], ah[mi], b0h, b1h);
                    mma16816(acc[mi][ni], ah[mi], b0l, b1l);
                    mma16816(acc[mi][ni], al[mi], b0h, b1h);
                }
        }
        __syncthreads();
    }

    // ---- epilogue: stage acc in smem, RoPE (Q/K) + split, store bf16 hi/lo ----
    float* Cs = (float*)smc;                       // 128 x 132 floats (67.6 KB)
    {
        const int rb = wr * 64 + (lane >> 2);
        const int cb2 = wc * 32 + (lane & 3) * 2;
        #pragma unroll
        for (int mi = 0; mi < 4; ++mi)
            #pragma unroll
            for (int ni = 0; ni < 4; ++ni) {
                int r = rb + mi * 16, cc = cb2 + ni * 8;
                Cs[r * 132 + cc]           = acc[mi][ni][0];
                Cs[r * 132 + cc + 1]       = acc[mi][ni][1];
                Cs[(r + 8) * 132 + cc]     = acc[mi][ni][2];
                Cs[(r + 8) * 132 + cc + 1] = acc[mi][ni][3];
            }
    }
    __syncthreads();

    __nv_bfloat16 *Hout, *Lout;
    int stride, off;
    bool dorope;
    if (bx < 32)      { Hout = Qh; Lout = Ql; stride = HID;  off = bx * 128;        dorope = true; }
    else if (bx < 40) { Hout = Kh; Lout = Kl; stride = NKVD; off = (bx - 32) * 128; dorope = true; }
    else              { Hout = Vh; Lout = Vl; stride = NKVD; off = (bx - 40) * 128; dorope = false; }

    const int d0 = tid & 63;       // rotation-pair column
    const int rg = tid >> 6;       // 0..3 -> 32 rows each
    const float invf = dorope ? expf(-(float)d0 * 0.14391156831212787f) : 0.f;

    #pragma unroll 4
    for (int rr = 0; rr < 32; ++rr) {
        const int r = rg * 32 + rr;
        const int t = m0 + r;
        float x0 = Cs[r * 132 + d0];
        float x1 = Cs[r * 132 + d0 + 64];
        float y0, y1;
        if (dorope) {
            float s, c;
            sincosf((float)pos[t] * invf, &s, &c);
            y0 = x0 * c - x1 * s;
            y1 = x1 * c + x0 * s;
        } else {
            y0 = x0; y1 = x1;
        }
        __nv_bfloat16 h0 = __float2bfloat16(y0);
        __nv_bfloat16 l0 = __float2bfloat16(y0 - __bfloat162float(h0));
        __nv_bfloat16 h1 = __float2bfloat16(y1);
        __nv_bfloat16 l1 = __float2bfloat16(y1 - __bfloat162float(h1));
        size_t o = (size_t)t * stride + off + d0;
        Hout[o]      = h0;
        Lout[o]      = l0;
        Hout[o + 64] = h1;
        Lout[o + 64] = l1;
    }
}

// ---------------------------------------------------------------------------
// Generic GEMM (Wo projection): C = (Ahi+Alo)*(Bhi+Blo)^T, fp32 out.
// ---------------------------------------------------------------------------
__global__ void __launch_bounds__(256, 1)
gemm_bf16x3(const __nv_bfloat16* __restrict__ Ahi, const __nv_bfloat16* __restrict__ Alo,
            const __nv_bfloat16* __restrict__ Bhi, const __nv_bfloat16* __restrict__ Blo,
            float* __restrict__ C, int M, int N, int K)
{
    extern __shared__ char smraw[];
    char* smc = (char*)(((uintptr_t)smraw + 1023) & ~(uintptr_t)1023);
    const uint32_t sbase = smem_u32(smc);

    const int tid = threadIdx.x;
    const int lane = tid & 31;
    const int wid = tid >> 5;
    const int wr = wid >> 2;
    const int wc = wid & 3;
    const int m0 = blockIdx.y * 128;
    const int n0 = blockIdx.x * 128;

    float acc[4][4][4];
    #pragma unroll
    for (int a = 0; a < 4; ++a)
        #pragma unroll
        for (int b = 0; b < 4; ++b)
            #pragma unroll
            for (int c = 0; c < 4; ++c) acc[a][b][c] = 0.f;

    const int NCHUNK = K / GK;

    auto load_chunk = [&](int it) {
        const uint32_t bufb = sbase + (it & 1) * BUFB;
        const int k0 = it * GK;
        #pragma unroll
        for (int p = 0; p < 4; ++p) {
            int linear = tid + p * 256;
            int r = linear >> 3;
            int cb = (linear & 7) * 16;
            uint32_t sw = SWZ((uint32_t)(r * 128 + cb));
            size_t ga = (size_t)(m0 + r) * K + k0 + (cb >> 1);
            size_t gb = (size_t)(n0 + r) * K + k0 + (cb >> 1);
            cp16(bufb + sw,              &Ahi[ga]);
            cp16(bufb + TILEB + sw,      &Alo[ga]);
            cp16(bufb + 2 * TILEB + sw,  &Bhi[gb]);
            cp16(bufb + 3 * TILEB + sw,  &Blo[gb]);
        }
    };

    load_chunk(0);
    cp_commit();

    const int lrow = lane & 15;
    const int lkb  = (lane >> 4) * 16;

    for (int it = 0; it < NCHUNK; ++it) {
        if (it + 1 < NCHUNK) {
            load_chunk(it + 1);
            cp_commit();
            cp_wait<1>();
        } else {
            cp_wait<0>();
        }
        __syncthreads();

        const uint32_t bufb = sbase + (it & 1) * BUFB;

        #pragma unroll
        for (int ks = 0; ks < 4; ++ks) {
            uint32_t ah[4][4], al[4][4], bh[2][4], bl[2][4];
            #pragma unroll
            for (int mi = 0; mi < 4; ++mi) {
                uint32_t off = (uint32_t)((wr * 64 + mi * 16 + lrow) * 128 + ks * 32 + lkb);
                uint32_t sw = SWZ(off);
                ldsm_x4(ah[mi], bufb + sw);
                ldsm_x4(al[mi], bufb + TILEB + sw);
            }
            #pragma unroll
            for (int np = 0; np < 2; ++np) {
                uint32_t off = (uint32_t)((wc * 32 + np * 16 + lrow) * 128 + ks * 32 + lkb);
                uint32_t sw = SWZ(off);
                ldsm_x4(bh[np], bufb + 2 * TILEB + sw);
                ldsm_x4(bl[np], bufb + 3 * TILEB + sw);
            }
            #pragma unroll
            for (int mi = 0; mi < 4; ++mi)
                #pragma unroll
                for (int ni = 0; ni < 4; ++ni) {
                    uint32_t b0h = bh[ni >> 1][ni & 1], b1h = bh[ni >> 1][2 + (ni & 1)];
                    uint32_t b0l = bl[ni >> 1][ni & 1], b1l = bl[ni >> 1][2 + (ni & 1)];
                    mma16816(acc[mi][ni], ah[mi], b0h, b1h);
                    mma16816(acc[mi][ni], ah[mi], b0l, b1l);
                    mma16816(acc[mi][ni], al[mi], b0h, b1h);
                }
        }
        __syncthreads();
    }

    const int row_base = m0 + wr * 64 + (lane >> 2);
    const int col_base = n0 + wc * 32 + (lane & 3) * 2;
    #pragma unroll
    for (int mi = 0; mi < 4; ++mi)
        #pragma unroll
        for (int ni = 0; ni < 4; ++ni) {
            int r = row_base + mi * 16;
            int cc = col_base + ni * 8;
            *(float2*)&C[(size_t)r * N + cc]       = make_float2(acc[mi][ni][0], acc[mi][ni][1]);
            *(float2*)&C[(size_t)(r + 8) * N + cc] = make_float2(acc[mi][ni][2], acc[mi][ni][3]);
        }
}

// ---------------------------------------------------------------------------
// Flash attention on tensor cores (bf16x3, online softmax in registers).
// ---------------------------------------------------------------------------
#define ATT_SMEM (1024 + 3 * 65536)

__global__ void __launch_bounds__(256)
attn_mma(const __nv_bfloat16* __restrict__ Qh_g, const __nv_bfloat16* __restrict__ Ql_g,
         const __nv_bfloat16* __restrict__ Kh_g, const __nv_bfloat16* __restrict__ Kl_g,
         const __nv_bfloat16* __restrict__ Vh_g, const __nv_bfloat16* __restrict__ Vl_g,
         __nv_bfloat16* __restrict__ Oh_g, __nv_bfloat16* __restrict__ Ol_g)
{
    extern __shared__ char smraw[];
    char* smc = (char*)(((uintptr_t)smraw + 1023) & ~(uintptr_t)1023);
    const uint32_t qbase = smem_u32(smc);
    const uint32_t kvbase = qbase + 65536;

    const int tid = threadIdx.x;
    const int lane = tid & 31;
    const int w = tid >> 5;
    const int wm = w * 16;
    const int m0 = blockIdx.x * 128;
    const int h = blockIdx.y;
    const int kvh = h >> 2;
    const int lrow = lane & 15;
    const int lhi = (lane >> 4) * 16;

    auto load_q = [&]() {
        #pragma unroll
        for (int p = 0; p < 16; ++p) {
            int lin = tid + p * 256;
            int t2 = lin >> 11;
            int rem = lin & 2047;
            int row = rem >> 4;
            int c = rem & 15;
            int half = c >> 3;
            int cb = (c & 7) * 16;
            uint32_t dst = qbase + t2 * 32768 + half * 16384
                         + SWZ((uint32_t)(row * 128 + cb));
            size_t elem = (size_t)(m0 + row) * HID + h * HDIM + half * 64 + (c & 7) * 8;
            cp16(dst, (t2 ? Ql_g : Qh_g) + elem);
        }
    };
    auto load_kv = [&](int j, int b) {
        const uint32_t base = kvbase + b * 65536;
        #pragma unroll
        for (int p = 0; p < 16; ++p) {
            int lin = tid + p * 256;
            int t4 = lin >> 10;
            int rem = lin & 1023;
            int row = rem >> 4;
            int c = rem & 15;
            int half = c >> 3;
            int cb = (c & 7) * 16;
            uint32_t dst = base + t4 * 16384 + half * 8192
                         + SWZ((uint32_t)(row * 128 + cb));
            size_t elem = (size_t)(j * 64 + row) * NKVD + kvh * HDIM
                        + half * 64 + (c & 7) * 8;
            const __nv_bfloat16* src =
                (t4 < 2) ? ((t4 & 1) ? Kl_g : Kh_g) : ((t4 & 1) ? Vl_g : Vh_g);
            cp16(dst, src + elem);
        }
    };

    const int j0 = (m0 >= 1024) ? (m0 - 1023) / 64 : 0;
    const int jend = m0 / 64 + 1;

    load_q();
    load_kv(j0, 0);
    cp_commit();

    float o[16][4];
    #pragma unroll
    for (int i = 0; i < 16; ++i)
        #pragma unroll
        for (int c = 0; c < 4; ++c) o[i][c] = 0.f;
    float mst0 = -INFINITY, mst1 = -INFINITY, lst0 = 0.f, lst1 = 0.f;

    const int row0 = m0 + wm + (lane >> 2);
    const int row1 = row0 + 8;
    const float scale = 0.08838834764831845f;

    for (int j = j0; j <= jend; ++j) {
        const int b = (j - j0) & 1;
        if (j + 1 <= jend) {
            load_kv(j + 1, b ^ 1);
            cp_commit();
            cp_wait<1>();
        } else {
            cp_wait<0>();
        }
        __syncthreads();

        const uint32_t kvb = kvbase + b * 65536;

        float sf[8][4];
        #pragma unroll
        for (int i = 0; i < 8; ++i)
            #pragma unroll
            for (int c = 0; c < 4; ++c) sf[i][c] = 0.f;

        #pragma unroll
        for (int kd = 0; kd < 8; ++kd) {
            const int half = kd >> 2;
            const uint32_t koff = (uint32_t)((kd & 3) * 32 + lhi);
            uint32_t ah[4], al[4], bh[4][4], bl[4][4];
            {
                uint32_t sw = SWZ((uint32_t)((wm + lrow) * 128) + koff);
                ldsm_x4(ah, qbase + half * 16384 + sw);
                ldsm_x4(al, qbase + 32768 + half * 16384 + sw);
            }
            #pragma unroll
            for (int nb = 0; nb < 4; ++nb) {
                uint32_t sw = SWZ((uint32_t)((nb * 16 + lrow) * 128) + koff);
                ldsm_x4(bh[nb], kvb + half * 8192 + sw);
                ldsm_x4(bl[nb], kvb + 16384 + half * 8192 + sw);
            }
            #pragma unroll
            for (int ni = 0; ni < 8; ++ni) {
                const int nb = ni >> 1, s = ni & 1;
                mma16816(sf[ni], ah, bh[nb][s], bh[nb][s + 2]);
                mma16816(sf[ni], ah, bl[nb][s], bl[nb][s + 2]);
                mma16816(sf[ni], al, bh[nb][s], bh[nb][s + 2]);
            }
        }

        const int colb = j * 64 + (lane & 3) * 2;
        float rmax0 = -INFINITY, rmax1 = -INFINITY;
        #pragma unroll
        for (int ni = 0; ni < 8; ++ni) {
            int c0 = colb + ni * 8, c1 = c0 + 1;
            sf[ni][0] = (c0 <= row0 && row0 - c0 < WINDOW) ? sf[ni][0] * scale : -INFINITY;
            sf[ni][1] = (c1 <= row0 && row0 - c1 < WINDOW) ? sf[ni][1] * scale : -INFINITY;
            sf[ni][2] = (c0 <= row1 && row1 - c0 < WINDOW) ? sf[ni][2] * scale : -INFINITY;
            sf[ni][3] = (c1 <= row1 && row1 - c1 < WINDOW) ? sf[ni][3] * scale : -INFINITY;
            rmax0 = fmaxf(rmax0, fmaxf(sf[ni][0], sf[ni][1]));
            rmax1 = fmaxf(rmax1, fmaxf(sf[ni][2], sf[ni][3]));
        }
        rmax0 = fmaxf(rmax0, __shfl_xor_sync(0xffffffffu, rmax0, 1));
        rmax0 = fmaxf(rmax0, __shfl_xor_sync(0xffffffffu, rmax0, 2));
        rmax1 = fmaxf(rmax1, __shfl_xor_sync(0xffffffffu, rmax1, 1));
        rmax1 = fmaxf(rmax1, __shfl_xor_sync(0xffffffffu, rmax1, 2));

        float mn0 = fmaxf(mst0, rmax0), mn1 = fmaxf(mst1, rmax1);
        float mc0 = fmaxf(mn0, -1e30f), mc1 = fmaxf(mn1, -1e30f);
        float a0 = __expf(fmaxf(mst0, -1e30f) - mc0);
        float a1 = __expf(fmaxf(mst1, -1e30f) - mc1);
        float sum0 = 0.f, sum1 = 0.f;
        #pragma unroll
        for (int ni = 0; ni < 8; ++ni) {
            sf[ni][0] = __expf(sf[ni][0] - mc0);
            sf[ni][1] = __expf(sf[ni][1] - mc0);
            sf[ni][2] = __expf(sf[ni][2] - mc1);
            sf[ni][3] = __expf(sf[ni][3] - mc1);
            sum0 += sf[ni][0] + sf[ni][1];
            sum1 += sf[ni][2] + sf[ni][3];
        }
        sum0 += __shfl_xor_sync(0xffffffffu, sum0, 1);
        sum0 += __shfl_xor_sync(0xffffffffu, sum0, 2);
        sum1 += __shfl_xor_sync(0xffffffffu, sum1, 1);
        sum1 += __shfl_xor_sync(0xffffffffu, sum1, 2);
        mst0 = mn0; mst1 = mn1;
        lst0 = lst0 * a0 + sum0;
        lst1 = lst1 * a1 + sum1;
        #pragma unroll
        for (int nf = 0; nf < 16; ++nf) {
            o[nf][0] *= a0; o[nf][1] *= a0;
            o[nf][2] *= a1; o[nf][3] *= a1;
        }

        #pragma unroll
        for (int ks = 0; ks < 4; ++ks) {
            uint32_t ah[4], al[4];
            packsplit(sf[2 * ks][0],     sf[2 * ks][1],     ah[0], al[0]);
            packsplit(sf[2 * ks][2],     sf[2 * ks][3],     ah[1], al[1]);
            packsplit(sf[2 * ks + 1][0], sf[2 * ks + 1][1], ah[2], al[2]);
            packsplit(sf[2 * ks + 1][2], sf[2 * ks + 1][3], ah[3], al[3]);
            #pragma unroll
            for (int g = 0; g < 8; ++g) {
                const int half = g >> 2;
                uint32_t off = SWZ((uint32_t)((ks * 16 + lrow) * 128 + (g & 3) * 32) + lhi);
                uint32_t vh[4], vl[4];
                ldsm_x4_t(vh, kvb + 32768 + half * 8192 + off);
                ldsm_x4_t(vl, kvb + 49152 + half * 8192 + off);
                mma16816(o[2 * g],     ah, vh[0], vh[1]);
                mma16816(o[2 * g],     ah, vl[0], vl[1]);
                mma16816(o[2 * g],     al, vh[0], vh[1]);
                mma16816(o[2 * g + 1], ah, vh[2], vh[3]);
                mma16816(o[2 * g + 1], ah, vl[2], vl[3]);
                mma16816(o[2 * g + 1], al, vh[2], vh[3]);
            }
        }
        __syncthreads();
    }

    const float inv0 = 1.f / lst0;
    const float inv1 = 1.f / lst1;
    #pragma unroll
    for (int nf = 0; nf < 16; ++nf) {
        int d = h * HDIM + nf * 8 + (lane & 3) * 2;
        size_t off0 = (size_t)row0 * HID + d;
        size_t off1 = (size_t)row1 * HID + d;
        uint32_t hi, lo;
        packsplit(o[nf][0] * inv0, o[nf][1] * inv0, hi, lo);
        *(uint32_t*)(Oh_g + off0) = hi;
        *(uint32_t*)(Ol_g + off0) = lo;
        packsplit(o[nf][2] * inv1, o[nf][3] * inv1, hi, lo);
        *(uint32_t*)(Oh_g + off1) = hi;
        *(uint32_t*)(Ol_g + off1) = lo;
    }
}

// ---------------------------------------------------------------------------
extern "C" void kernel_launch(void* const* d_in, const int* in_sizes, int n_in,
                              void* d_out, int out_size)
{
    const float* hs  = (const float*)d_in[0];
    const int*   pos = (const int*)d_in[2];
    const float* Wq  = (const float*)d_in[3];
    const float* Wk  = (const float*)d_in[4];
    const float* Wv  = (const float*)d_in[5];
    const float* Wo  = (const float*)d_in[6];
    float* out = (float*)d_out;

    __nv_bfloat16 *hsh, *hsl, *ath, *atl, *wqh, *wql, *wkh, *wkl, *wvh, *wvl, *woh, *wol;
    __nv_bfloat16 *qhh, *qll, *khh, *kll, *vhh, *vll;
    cudaGetSymbolAddress((void**)&hsh, g_hs_hi);  cudaGetSymbolAddress((void**)&hsl, g_hs_lo);
    cudaGetSymbolAddress((void**)&ath, g_att_hi); cudaGetSymbolAddress((void**)&atl, g_att_lo);
    cudaGetSymbolAddress((void**)&wqh, g_Wq_hi);  cudaGetSymbolAddress((void**)&wql, g_Wq_lo);
    cudaGetSymbolAddress((void**)&wkh, g_Wk_hi);  cudaGetSymbolAddress((void**)&wkl, g_Wk_lo);
    cudaGetSymbolAddress((void**)&wvh, g_Wv_hi);  cudaGetSymbolAddress((void**)&wvl, g_Wv_lo);
    cudaGetSymbolAddress((void**)&woh, g_Wo_hi);  cudaGetSymbolAddress((void**)&wol, g_Wo_lo);
    cudaGetSymbolAddress((void**)&qhh, g_Qh);     cudaGetSymbolAddress((void**)&qll, g_Ql);
    cudaGetSymbolAddress((void**)&khh, g_Kh);     cudaGetSymbolAddress((void**)&kll, g_Kl);
    cudaGetSymbolAddress((void**)&vhh, g_Vh);     cudaGetSymbolAddress((void**)&vll, g_Vl);

    const int gemm_smem = 1024 + 2 * BUFB;
    cudaFuncSetAttribute(gemm_qkv, cudaFuncAttributeMaxDynamicSharedMemorySize, gemm_smem);
    cudaFuncSetAttribute(gemm_bf16x3, cudaFuncAttributeMaxDynamicSharedMemorySize, gemm_smem);
    cudaFuncSetAttribute(attn_mma, cudaFuncAttributeMaxDynamicSharedMemorySize, ATT_SMEM);

    // split fp32 inputs -> bf16 hi/lo (launches 0..4)
    {
        int n;
        n = S_LEN * HID / 4;   split_kernel<<<(n + 255) / 256, 256>>>(hs, hsh, hsl, n);
        n = HID * HID / 4;     split_kernel<<<(n + 255) / 256, 256>>>(Wq, wqh, wql, n);
        n = NKVD * HID / 4;    split_kernel<<<(n + 255) / 256, 256>>>(Wk, wkh, wkl, n);
        n = NKVD * HID / 4;    split_kernel<<<(n + 255) / 256, 256>>>(Wv, wvh, wvl, n);
        n = HID * HID / 4;     split_kernel<<<(n + 255) / 256, 256>>>(Wo, woh, wol, n);
    }

    // fused QKV projection + RoPE + split (launch 5 — ncu -s 5 target)
    gemm_qkv<<<dim3(48, 16), 256, gemm_smem>>>(hsh, hsl, pos,
                                               qhh, qll, khh, kll, vhh, vll);

    // attention (tensor cores), writes bf16 hi/lo directly
    attn_mma<<<dim3(S_LEN / 128, NH), 256, ATT_SMEM>>>(qhh, qll, khh, kll, vhh, vll, ath, atl);

    // output projection
    gemm_bf16x3<<<dim3(HID / 128, S_LEN / 128), 256, gemm_smem>>>(ath, atl, woh, wol, out, S_LEN, HID, KDIM);
}